// round 17
// baseline (speedup 1.0000x reference)
#include <cuda_runtime.h>
#include <cuda_fp16.h>
#include <cstdint>

// ============================================================================
// Problem constants
// ============================================================================
#define B_DIM 32768
#define H_DIM 512
#define KTOT  1024   // E + H
#define NTOT  2048   // 4*H

// GEMM tiling
#define BM 128
#define BN 128
#define BK 64              // halves per K-chunk
#define NKIT (KTOT / BK)   // 16
#define STAGES 3
#define ROWB 144           // 128B data + 16B pad per row (conflict-free ldmatrix)
#define TILE_BYTES (128 * ROWB)           // 18432
#define STAGE_BYTES (2 * TILE_BYTES)      // 36864
#define SMEM_TOTAL (STAGES * STAGE_BYTES) // 110592 -> 2 CTA/SM
// epilogue: csm f32 (128 x 132 = 67584B) at 0; f16 park region above it
#define CSTRIDE 132
#define HREG_OFF (2 * STAGE_BYTES)        // 73728; +128*272 = 108544 <= 110592
#define HREG_ROWB 272                     // 136 halves per row

#define NTHREADS 256       // 8 warps: kshalf(2) x warpN(2) x warpM(2), tile 64x64, occ 2

// convert grid split
#define A_BLOCKS ((B_DIM * KTOT) / 4 / 256)   // 32768
#define W_BLOCKS ((NTOT * KTOT) / 4 / 256)    // 2048

// ============================================================================
// Scratch (device globals — allocation-free)
// ============================================================================
__device__ __half g_A[(size_t)B_DIM * KTOT];   // 64 MB: [x | h0] fp16
__device__ __half g_W[(size_t)NTOT * KTOT];    // 4 MB: gate-interleaved [W_x | W_h]
__device__ float  g_bias[NTOT];                // b_x + b_h, gate-interleaved

// ============================================================================
// PTX helpers (compute_103-safe: legacy mma + Ampere mbarrier/cp.async)
// ============================================================================
__device__ __forceinline__ uint32_t smem_u32(const void* p) {
    uint32_t a;
    asm("{ .reg .u64 t; cvta.to.shared.u64 t, %1; cvt.u32.u64 %0, t; }" : "=r"(a) : "l"(p));
    return a;
}

__device__ __forceinline__ void cp16(uint32_t saddr, const void* gaddr) {
    asm volatile("cp.async.cg.shared.global [%0], [%1], 16;" :: "r"(saddr), "l"(gaddr) : "memory");
}

#define MBARRIER_INIT(addr, cnt) \
    asm volatile("mbarrier.init.shared.b64 [%0], %1;" :: "r"((uint32_t)(addr)), "r"((uint32_t)(cnt)) : "memory")

#define MBARRIER_ARRIVE(addr) \
    asm volatile("mbarrier.arrive.shared.b64 _, [%0];" :: "r"((uint32_t)(addr)) : "memory")

#define CP_ASYNC_MBAR_ARRIVE(addr) \
    asm volatile("cp.async.mbarrier.arrive.noinc.shared.b64 [%0];" :: "r"((uint32_t)(addr)) : "memory")

// try_wait with HW-sleep hint: spinning warps stop stealing issue slots
#define MBAR_WAIT(addr, parity) do {                                                    \
    uint32_t _m = (uint32_t)(addr);                                                     \
    uint32_t _p = (uint32_t)(parity);                                                   \
    uint32_t _done;                                                                     \
    asm volatile("{\n\t.reg .pred p;\n\t"                                               \
        "mbarrier.try_wait.parity.shared.b64 p, [%1], %2;\n\t"                          \
        "selp.b32 %0, 1, 0, p;\n\t}"                                                    \
        : "=r"(_done) : "r"(_m), "r"(_p) : "memory");                                   \
    if (!_done) {                                                                       \
        asm volatile("{\n\t.reg .pred P1;\n\t"                                          \
            "WL_%=:\n\t"                                                                \
            "mbarrier.try_wait.parity.shared.b64 P1, [%0], %1, 0x989680;\n\t"           \
            "@P1 bra.uni WD_%=;\n\t"                                                    \
            "bra.uni WL_%=;\n\t"                                                        \
            "WD_%=:\n\t}"                                                               \
            :: "r"(_m), "r"(_p) : "memory");                                            \
    }                                                                                   \
} while (0)

__device__ __forceinline__ void ldsm_x4(uint32_t& r0, uint32_t& r1, uint32_t& r2, uint32_t& r3,
                                        uint32_t addr) {
    asm volatile("ldmatrix.sync.aligned.m8n8.x4.shared.b16 {%0,%1,%2,%3}, [%4];"
                 : "=r"(r0), "=r"(r1), "=r"(r2), "=r"(r3) : "r"(addr));
}

// f16-accumulate mma (rt ~8/SMSP confirmed by R8-R16 profiles)
__device__ __forceinline__ void mma16816_f16(uint32_t& d0, uint32_t& d1,
                                             uint32_t a0, uint32_t a1, uint32_t a2, uint32_t a3,
                                             uint32_t b0, uint32_t b1) {
    asm volatile("mma.sync.aligned.m16n8k16.row.col.f16.f16.f16.f16 "
                 "{%0,%1}, {%2,%3,%4,%5}, {%6,%7}, {%0,%1};"
                 : "+r"(d0), "+r"(d1)
                 : "r"(a0), "r"(a1), "r"(a2), "r"(a3), "r"(b0), "r"(b1));
}

// ============================================================================
// Merged convert pass: A = [x|h0] -> fp16 ; W gate-interleaved -> fp16 ; bias
// ============================================================================
__global__ __launch_bounds__(256) void convert_all_kernel(
        const float* __restrict__ x,  const float* __restrict__ h0,
        const float* __restrict__ Wx, const float* __restrict__ Wh,
        const float* __restrict__ bx, const float* __restrict__ bh) {
    if (blockIdx.x < A_BLOCKS) {
        int g = blockIdx.x * 256 + threadIdx.x;   // group of 4 elements
        int b = g >> 8;
        int cg = g & 255;
        const float* src = (cg < 128) ? (x + b * 512 + cg * 4)
                                      : (h0 + b * 512 + (cg - 128) * 4);
        float4 v = *reinterpret_cast<const float4*>(src);
        __half2 lo = __floats2half2_rn(v.x, v.y);
        __half2 hi = __floats2half2_rn(v.z, v.w);
        uint2 u;
        u.x = *reinterpret_cast<const unsigned*>(&lo);
        u.y = *reinterpret_cast<const unsigned*>(&hi);
        *reinterpret_cast<uint2*>(g_A + (size_t)g * 4) = u;
    } else {
        int g = (blockIdx.x - A_BLOCKS) * 256 + threadIdx.x;
        int r = g >> 8;           // dest row = h*4 + k
        int cg = g & 255;
        int k = r & 3;
        int h = r >> 2;
        int c = cg * 4;
        const float* src = (cg < 128) ? (Wx + (k * 512 + h) * 512 + c)
                                      : (Wh + (k * 512 + h) * 512 + (c - 512));
        float4 v = *reinterpret_cast<const float4*>(src);
        __half2 lo = __floats2half2_rn(v.x, v.y);
        __half2 hi = __floats2half2_rn(v.z, v.w);
        uint2 u;
        u.x = *reinterpret_cast<const unsigned*>(&lo);
        u.y = *reinterpret_cast<const unsigned*>(&hi);
        *reinterpret_cast<uint2*>(g_W + (size_t)g * 4) = u;

        if (blockIdx.x == A_BLOCKS) {
            for (int rr = threadIdx.x; rr < NTOT; rr += 256) {
                int kk = rr & 3, hh = rr >> 2;
                g_bias[rr] = bx[kk * 512 + hh] + bh[kk * 512 + hh];
            }
        }
    }
}

// ============================================================================
// Fused GEMM: R16 loop mechanics x R12 traffic shape.
//   8 warps: kshalf(2) x warpN(2) x warpM(2), warp tile 64x64, occ 2.
//   In-order single ring; each warp consumes only its 2 ks-subchunks per stage
//   (kshalf 0 -> ks{0,1}, kshalf 1 -> ks{2,3}); produce interleaved between them.
//   Single f16 acc (64 regs, K=512/warp — validated numerics), fp32 combine once.
// ============================================================================

// consume one ks-subchunk (byte offset KSOFF within this group's window)
#define CONSUME_KS(ACC, KSOFF)                                                    \
    do {                                                                          \
        uint32_t a[4][4];                                                         \
        _Pragma("unroll")                                                         \
        for (int mt = 0; mt < 4; mt++)                                            \
            ldsm_x4(a[mt][0], a[mt][1], a[mt][2], a[mt][3],                       \
                    abase + a_lane_off + (uint32_t)(mt * 16 * ROWB) + (KSOFF));   \
        uint32_t b[8][2];                                                         \
        _Pragma("unroll")                                                         \
        for (int ntp = 0; ntp < 4; ntp++) {                                       \
            uint32_t r0, r1, r2, r3;                                              \
            ldsm_x4(r0, r1, r2, r3,                                               \
                    bbase + b_lane_off + (uint32_t)(ntp * 16 * ROWB) + (KSOFF));  \
            b[2 * ntp + 0][0] = r0; b[2 * ntp + 0][1] = r1;                       \
            b[2 * ntp + 1][0] = r2; b[2 * ntp + 1][1] = r3;                       \
        }                                                                         \
        _Pragma("unroll")                                                         \
        for (int mt = 0; mt < 4; mt++)                                            \
            _Pragma("unroll")                                                     \
            for (int nt = 0; nt < 8; nt++)                                        \
                mma16816_f16(ACC[mt][nt][0], ACC[mt][nt][1],                      \
                             a[mt][0], a[mt][1], a[mt][2], a[mt][3],              \
                             b[nt][0], b[nt][1]);                                 \
    } while (0)

// produce stage pstage from hoisted pointers at K offset K0 (halves)
#define PRODUCE_STAGE(K0)                                                         \
    do {                                                                          \
        MBAR_WAIT(mb + 8 * (STAGES + pstage), pphase);                            \
        uint32_t ab = sb + pstage * STAGE_BYTES + doff;                           \
        _Pragma("unroll")                                                         \
        for (int j = 0; j < 4; j++) {                                             \
            cp16(ab + (uint32_t)(j * 32 * ROWB), srcA0 + (K0) + j * 32 * KTOT);   \
            cp16(ab + (uint32_t)(TILE_BYTES + j * 32 * ROWB),                     \
                 srcW0 + (K0) + j * 32 * KTOT);                                   \
        }                                                                         \
        CP_ASYNC_MBAR_ARRIVE(mb + 8 * pstage);                                    \
        if (++pstage == STAGES) { pstage = 0; pphase ^= 1; }                      \
    } while (0)

// full k-iteration: wait, mma own ks_a, produce kt+2 (hidden), mma own ks_b, free
#define K_ITER(ACC, KT)                                                           \
    do {                                                                          \
        MBAR_WAIT(mb + 8 * cstage, cphase);                                       \
        const uint32_t abase = sb + cstage * STAGE_BYTES;                         \
        const uint32_t bbase = abase + TILE_BYTES;                                \
        CONSUME_KS(ACC, 0u);                                                      \
        if ((KT) + 2 < NKIT) PRODUCE_STAGE(((KT) + 2) * BK);                      \
        CONSUME_KS(ACC, 32u);                                                     \
        MBARRIER_ARRIVE(mb + 8 * (STAGES + cstage));                              \
        if (++cstage == STAGES) { cstage = 0; cphase ^= 1; }                      \
    } while (0)

__global__ __launch_bounds__(NTHREADS, 2) void lstm_gemm_kernel(const float* __restrict__ c0,
                                                                float* __restrict__ out) {
    extern __shared__ char smem[];
    __shared__ uint64_t s_mbar[2 * STAGES];   // [full 0..2 | empty 0..2]
    const uint32_t sb = smem_u32(smem);
    const uint32_t mb = smem_u32(s_mbar);
    const int tid = threadIdx.x;
    const int wid = tid >> 5;
    const int lane = tid & 31;
    const int n0 = blockIdx.x * BN;   // N fastest -> CTAs sharing A run together
    const int m0 = blockIdx.y * BM;

    const int kshalf = wid >> 2;      // 0: ks {0,1}, 1: ks {2,3}
    const int warpN = (wid >> 1) & 1; // 2 N-warps of 64 cols
    const int warpM = wid & 1;        // 2 M-warps of 64 rows

    if (tid == 0) {
#pragma unroll
        for (int s = 0; s < STAGES; s++) {
            MBARRIER_INIT(mb + 8 * s, NTHREADS);               // full[s]
            MBARRIER_INIT(mb + 8 * (STAGES + s), NTHREADS);    // empty[s]
        }
    }
    __syncthreads();

    // hoisted producer addressing (src pointers invariant up to +K0)
    const uint32_t doff = (uint32_t)((tid >> 3) * ROWB + (tid & 7) * 16);
    const __half* srcA0 = g_A + (size_t)(m0 + (tid >> 3)) * KTOT + (tid & 7) * 8;
    const __half* srcW0 = g_W + (size_t)(n0 + (tid >> 3)) * KTOT + (tid & 7) * 8;

    // ldmatrix per-lane base offsets incl. this group's ks window (64B per half)
    const uint32_t ks_base = (uint32_t)(kshalf * 64);
    const uint32_t a_lane_off = (uint32_t)((warpM * 64 + (lane & 15)) * ROWB
                                           + ((lane >> 4) & 1) * 16) + ks_base;
    const uint32_t b_lane_off = (uint32_t)((warpN * 64 + (lane & 7) + ((lane >> 4) & 1) * 8) * ROWB
                                           + ((lane >> 3) & 1) * 16) + ks_base;

    int pstage = 0, pphase = 1;  // producer (phase 1 -> first empty-waits pass)
    int cstage = 0, cphase = 0;  // consumer (in-order, every stage)

    // Prologue: fill stages 0,1
    PRODUCE_STAGE(0 * BK);
    PRODUCE_STAGE(1 * BK);

    // Single f16 accumulator set: warp tile 64x64 -> [mt][nt][2] = 64 regs
    uint32_t acc[4][8][2];
#pragma unroll
    for (int mt = 0; mt < 4; mt++)
#pragma unroll
        for (int nt = 0; nt < 8; nt++) { acc[mt][nt][0] = 0u; acc[mt][nt][1] = 0u; }

#pragma unroll 1
    for (int kt = 0; kt < NKIT; kt++) {
        K_ITER(acc, kt);
    }

    // -------- Epilogue --------
    __syncthreads();   // all consumption done; stage buffers reusable

    // Phase 1: kshalf-1 warps park f16 accs in smem (they cover the full 128x128)
    const int rbase = warpM * 64 + (lane >> 2);
    const int cbase = warpN * 64 + 2 * (lane & 3);
    if (kshalf == 1) {
#pragma unroll
        for (int mt = 0; mt < 4; mt++)
#pragma unroll
            for (int nt = 0; nt < 8; nt++) {
                int r = rbase + mt * 16;
                int c = cbase + nt * 8;
                *reinterpret_cast<uint32_t*>(smem + HREG_OFF + r * HREG_ROWB + c * 2) = acc[mt][nt][0];
                *reinterpret_cast<uint32_t*>(smem + HREG_OFF + (r + 8) * HREG_ROWB + c * 2) = acc[mt][nt][1];
            }
    }
    __syncthreads();

    // Phase 2: kshalf-0 warps promote own + partner to fp32, stage into csm
    float* csm = reinterpret_cast<float*>(smem);
    if (kshalf == 0) {
#pragma unroll
        for (int mt = 0; mt < 4; mt++)
#pragma unroll
            for (int nt = 0; nt < 8; nt++) {
                int r = rbase + mt * 16;
                int c = cbase + nt * 8;
                uint32_t p0 = *reinterpret_cast<uint32_t*>(smem + HREG_OFF + r * HREG_ROWB + c * 2);
                uint32_t p1 = *reinterpret_cast<uint32_t*>(smem + HREG_OFF + (r + 8) * HREG_ROWB + c * 2);
                float2 o0 = __half22float2(*reinterpret_cast<__half2*>(&acc[mt][nt][0]));
                float2 o1 = __half22float2(*reinterpret_cast<__half2*>(&acc[mt][nt][1]));
                float2 q0 = __half22float2(*reinterpret_cast<__half2*>(&p0));
                float2 q1 = __half22float2(*reinterpret_cast<__half2*>(&p1));
                *reinterpret_cast<float2*>(csm + r * CSTRIDE + c) =
                    make_float2(o0.x + q0.x, o0.y + q0.y);
                *reinterpret_cast<float2*>(csm + (r + 8) * CSTRIDE + c) =
                    make_float2(o1.x + q1.x, o1.y + q1.y);
            }
    }
    __syncthreads();

    // Phase 3: fused LSTM gates, fully coalesced outputs
    {
        const int hbase = n0 >> 2;                  // 32 hidden units per CTA tile
        const int h = hbase + lane;
        float4 bias = *reinterpret_cast<const float4*>(g_bias + n0 + lane * 4);
#pragma unroll 4
        for (int it = 0; it < 16; it++) {
            int row = wid + 8 * it;                 // 8 warps x 16 iters = 128 rows
            int b = m0 + row;
            float4 z = *reinterpret_cast<const float4*>(csm + row * CSTRIDE + lane * 4);
            float zi = z.x + bias.x;
            float zf = z.y + bias.y;
            float zo = z.z + bias.z;
            float zg = z.w + bias.w;
            float ig = 1.0f / (1.0f + __expf(-zi));
            float fg = 1.0f / (1.0f + __expf(-zf));
            float og = 1.0f / (1.0f + __expf(-zo));
            float gg = tanhf(zg);
            float c1 = fg * __ldg(c0 + (size_t)b * H_DIM + h) + ig * gg;
            float h1 = og * tanhf(c1);
            out[(size_t)b * H_DIM + h] = h1;                                  // h1
            out[(size_t)B_DIM * H_DIM + (size_t)b * H_DIM + h] = c1;          // c1
        }
    }
}

// ============================================================================
// kernel_launch
// ============================================================================
extern "C" void kernel_launch(void* const* d_in, const int* in_sizes, int n_in,
                              void* d_out, int out_size) {
    (void)in_sizes; (void)n_in; (void)out_size;
    const float* x  = (const float*)d_in[0];
    const float* h0 = (const float*)d_in[1];
    const float* c0 = (const float*)d_in[2];
    const float* Wx = (const float*)d_in[3];
    const float* bx = (const float*)d_in[4];
    const float* Wh = (const float*)d_in[5];
    const float* bh = (const float*)d_in[6];
    float* out = (float*)d_out;

    convert_all_kernel<<<A_BLOCKS + W_BLOCKS, 256>>>(x, h0, Wx, Wh, bx, bh);

    cudaFuncSetAttribute(lstm_gemm_kernel, cudaFuncAttributeMaxDynamicSharedMemorySize, SMEM_TOTAL);
    dim3 grid(NTOT / BN, B_DIM / BM);   // (16, 256), N fastest
    lstm_gemm_kernel<<<grid, NTHREADS, SMEM_TOTAL>>>(c0, out);
}